// round 2
// baseline (speedup 1.0000x reference)
#include <cuda_runtime.h>
#include <cuda_bf16.h>
#include <cuda_pipeline.h>
#include <math.h>

// B=32, IU=128, OU=128, ID=64, VD=64
// mean-votes GEMM: mv[b][n] = (1/128) * sum_{i,e} x[b,i,e] * W[i, n*64... ], n=o*64+d, N=8192, K=8192

#define FMA2(a, xx, ww) asm("fma.rn.f32x2 %0, %1, %2, %0;" : "+l"(a) : "l"(xx), "l"(ww))

// ---------------- scratch ----------------
__device__ float g_part[2][32 * 8192];   // K-split partials
__device__ float g_nv[32 * 8192];        // layernormed norm_value (b, o*64+d)
__device__ float g_q[32 * 128 * 64];
__device__ float g_k[32 * 128 * 64];
__device__ float g_k2[32 * 128 * 64];
__device__ float g_agg[32 * 128 * 64];
__device__ float g_wvo[2][64 * 64];
__device__ float g_bvo[2][64];

// ---------------- mean-votes GEMM ----------------
constexpr int WSP = 68;                        // padded w-row stride (floats)
constexpr int WS_ELEMS = 128 * WSP;            // 8704
constexpr int XS_ELEMS = 32 * 64;              // 2048
constexpr int GEMM_SMEM = 2 * (WS_ELEMS + XS_ELEMS) * 4;   // 86016 B

__global__ __launch_bounds__(128, 1)
void votes_gemm_kernel(const float* __restrict__ X, const float* __restrict__ W) {
    extern __shared__ float sm[];
    float* wsbuf[2] = { sm, sm + WS_ELEMS };
    float* xsbuf[2] = { sm + 2 * WS_ELEMS, sm + 2 * WS_ELEMS + XS_ELEMS };
    const int tid = threadIdx.x;
    const int nb  = blockIdx.x;      // 0..63  (128 n-cols each)
    const int ks  = blockIdx.y;      // 0..1   (64 i's each)
    const int i0  = ks * 64;

    auto load_stage = [&](int stage, int i) {
        const float* wsrc = W + (size_t)i * 524288 + (size_t)nb * 8192;  // contiguous 128n x 64e
        float* wd = wsbuf[stage];
        #pragma unroll
        for (int c = tid; c < 2048; c += 128) {          // 2048 x 16B chunks = 32KB
            int n = c >> 4, e4 = c & 15;
            __pipeline_memcpy_async(&wd[n * WSP + e4 * 4], wsrc + c * 4, 16);
        }
        float* xd = xsbuf[stage];
        #pragma unroll
        for (int c = tid; c < 512; c += 128) {           // 32b x 64e = 8KB
            int b = c >> 4, e4 = c & 15;
            __pipeline_memcpy_async(&xd[b * 64 + e4 * 4],
                                    X + (size_t)b * 8192 + (size_t)i * 64 + e4 * 4, 16);
        }
        __pipeline_commit();
    };

    load_stage(0, i0);

    unsigned long long acc[8][4];
    #pragma unroll
    for (int bb = 0; bb < 8; ++bb)
        #pragma unroll
        for (int nn = 0; nn < 4; ++nn) acc[bb][nn] = 0ULL;

    const int warp = tid >> 5;       // b-group: whole warp shares b rows -> x reads broadcast
    const int lane = tid & 31;       // w row: stride 68 -> conflict-free LDS.128 phases
    const int brow = warp * 8;

    for (int it = 0; it < 64; ++it) {
        const int st = it & 1;
        if (it + 1 < 64) { load_stage(st ^ 1, i0 + it + 1); __pipeline_wait_prior(1); }
        else             { __pipeline_wait_prior(0); }
        __syncthreads();

        const float* wsp = wsbuf[st];
        const float* xsp = xsbuf[st];
        #pragma unroll 2
        for (int e4 = 0; e4 < 16; ++e4) {
            ulonglong2 xv[8], wv[4];
            #pragma unroll
            for (int bb = 0; bb < 8; ++bb)
                xv[bb] = *(const ulonglong2*)&xsp[(brow + bb) * 64 + e4 * 4];
            #pragma unroll
            for (int nn = 0; nn < 4; ++nn)
                wv[nn] = *(const ulonglong2*)&wsp[(lane + 32 * nn) * WSP + e4 * 4];
            #pragma unroll
            for (int bb = 0; bb < 8; ++bb)
                #pragma unroll
                for (int nn = 0; nn < 4; ++nn) {
                    FMA2(acc[bb][nn], xv[bb].x, wv[nn].x);   // (e, e+1)
                    FMA2(acc[bb][nn], xv[bb].y, wv[nn].y);   // (e+2, e+3)
                }
        }
        __syncthreads();
    }

    float* dst = &g_part[ks][0] + nb * 128;
    #pragma unroll
    for (int bb = 0; bb < 8; ++bb)
        #pragma unroll
        for (int nn = 0; nn < 4; ++nn) {
            float lo, hi;
            asm("mov.b64 {%0, %1}, %2;" : "=f"(lo), "=f"(hi) : "l"(acc[bb][nn]));
            dst[(size_t)(brow + bb) * 8192 + lane + 32 * nn] = lo + hi;
        }
}

// ---------------- K-split reduce + 1/128 + layernorm over d=64 ----------------
__global__ __launch_bounds__(32)
void ln_kernel(const float* __restrict__ lng, const float* __restrict__ lnb) {
    const int base = blockIdx.x * 64;         // row = b*128 + o
    const int t = threadIdx.x;                // 32 threads, 2 d's each
    float v0 = (g_part[0][base + t]      + g_part[1][base + t])      * (1.0f / 128.0f);
    float v1 = (g_part[0][base + t + 32] + g_part[1][base + t + 32]) * (1.0f / 128.0f);
    float s  = v0 + v1;
    float sq = v0 * v0 + v1 * v1;
    #pragma unroll
    for (int off = 16; off; off >>= 1) {
        s  += __shfl_xor_sync(0xffffffffu, s,  off);
        sq += __shfl_xor_sync(0xffffffffu, sq, off);
    }
    float mean = s * (1.0f / 64.0f);
    float var  = sq * (1.0f / 64.0f) - mean * mean;
    float rstd = rsqrtf(var + 1e-6f);
    g_nv[base + t]      = (v0 - mean) * rstd * lng[t]      + lnb[t];
    g_nv[base + t + 32] = (v1 - mean) * rstd * lng[t + 32] + lnb[t + 32];
}

// ---------------- fused value-output weights: wvo = wv@wo, bvo = bv@wo + bo ----------------
__global__ __launch_bounds__(256)
void wvo_kernel(const float* wv1, const float* wo1, const float* bv1, const float* bo1,
                const float* wv2, const float* wo2, const float* bv2, const float* bo2) {
    const int a = blockIdx.x;
    const float* wv = a ? wv2 : wv1; const float* wo = a ? wo2 : wo1;
    const float* bv = a ? bv2 : bv1; const float* bo = a ? bo2 : bo1;
    __shared__ float wos[4096];
    const int t = threadIdx.x + threadIdx.y * 64;      // blockDim (64,4)
    for (int idx = t; idx < 4096; idx += 256) wos[idx] = wo[idx];
    __syncthreads();
    const int j = threadIdx.x;
    #pragma unroll 4
    for (int dd = 0; dd < 16; ++dd) {
        int d = threadIdx.y * 16 + dd;
        float s = 0.f;
        #pragma unroll
        for (int e = 0; e < 64; ++e) s += wv[d * 64 + e] * wos[e * 64 + j];
        g_wvo[a][d * 64 + j] = s;
    }
    if (threadIdx.y == 0) {
        float s = 0.f;
        #pragma unroll
        for (int e = 0; e < 64; ++e) s += bv[e] * wos[e * 64 + j];
        g_bvo[a][j] = s + bo[j];
    }
}

// ---------------- row projection: out[r,:] = in[r,:]@w + bias, 4096 rows ----------------
__global__ __launch_bounds__(512)
void proj_kernel(const float* __restrict__ in, const float* __restrict__ w,
                 const float* __restrict__ bias, float* __restrict__ out) {
    __shared__ float ws[4096];
    __shared__ float ins[512];
    const int t = threadIdx.x + threadIdx.y * 64;      // blockDim (64,8)
    for (int idx = t; idx < 4096; idx += 512) ws[idx] = w[idx];
    const int row0 = blockIdx.x * 8;
    ins[t] = in[row0 * 64 + t];
    __syncthreads();
    const int j = threadIdx.x, r = threadIdx.y;
    float acc = bias[j];
    #pragma unroll
    for (int e = 0; e < 64; ++e) acc += ins[r * 64 + e] * ws[e * 64 + j];
    out[(row0 + r) * 64 + j] = acc;
}

// ---------------- attention: scores=softmax(Q K^T/8); out=(S@Vsrc)@wvo + bvo ----------------
__global__ __launch_bounds__(128)
void attn_kernel(const float* __restrict__ Q, const float* __restrict__ K,
                 const float* __restrict__ Vsrc,
                 const float* __restrict__ wvo, const float* __restrict__ bvo,
                 float* scores_out, float* val_out, float* val_out2) {
    __shared__ float kv[128 * 68];     // K tile, then V tile, then wvo
    __shared__ float sc[16 * 132];     // softmax probabilities
    __shared__ float qs[16 * 68];      // Q tile, then ctx
    const int t = threadIdx.x;
    const int b = blockIdx.y, qt = blockIdx.x;
    const int q0 = qt * 16;

    const float* Qb = Q + b * 8192 + q0 * 64;
    for (int idx = t; idx < 1024; idx += 128) qs[(idx >> 6) * 68 + (idx & 63)] = Qb[idx];
    const float* Kb = K + b * 8192;
    for (int idx = t; idx < 8192; idx += 128) kv[(idx >> 6) * 68 + (idx & 63)] = Kb[idx];
    __syncthreads();

    const int q = t >> 3, kg = t & 7;           // 8 threads per q row; k = kg + 8*rep
    float acc[16];
    #pragma unroll
    for (int rep = 0; rep < 16; ++rep) acc[rep] = 0.f;
    #pragma unroll
    for (int e4 = 0; e4 < 16; ++e4) {
        float4 qv = *(const float4*)&qs[q * 68 + e4 * 4];
        #pragma unroll
        for (int rep = 0; rep < 16; ++rep) {
            float4 kvv = *(const float4*)&kv[(kg + 8 * rep) * 68 + e4 * 4];
            acc[rep] += qv.x * kvv.x + qv.y * kvv.y + qv.z * kvv.z + qv.w * kvv.w;
        }
    }
    // softmax over the 8-lane group (each holds 16 of 128 k's)
    float m = -1e30f;
    #pragma unroll
    for (int rep = 0; rep < 16; ++rep) { acc[rep] *= 0.125f; m = fmaxf(m, acc[rep]); }
    #pragma unroll
    for (int off = 1; off < 8; off <<= 1) m = fmaxf(m, __shfl_xor_sync(0xffffffffu, m, off));
    float ssum = 0.f;
    #pragma unroll
    for (int rep = 0; rep < 16; ++rep) { acc[rep] = __expf(acc[rep] - m); ssum += acc[rep]; }
    #pragma unroll
    for (int off = 1; off < 8; off <<= 1) ssum += __shfl_xor_sync(0xffffffffu, ssum, off);
    const float inv = 1.0f / ssum;
    float* so = scores_out ? scores_out + b * 16384 + (q0 + q) * 128 : nullptr;
    #pragma unroll
    for (int rep = 0; rep < 16; ++rep) {
        float p = acc[rep] * inv;
        acc[rep] = p;
        sc[q * 132 + kg + 8 * rep] = p;
        if (so) so[kg + 8 * rep] = p;
    }
    __syncthreads();

    // V tile
    const float* Vb = Vsrc + b * 8192;
    for (int idx = t; idx < 8192; idx += 128) kv[(idx >> 6) * 68 + (idx & 63)] = Vb[idx];
    __syncthreads();

    // ctx[q][d] = sum_k p * V[k][d] ; thread handles d = dg*8..dg*8+7
    const int dg = t & 7;
    float c[8];
    #pragma unroll
    for (int i = 0; i < 8; ++i) c[i] = 0.f;
    for (int k = 0; k < 128; ++k) {
        float p = sc[q * 132 + k];
        float4 v1 = *(const float4*)&kv[k * 68 + dg * 8];
        float4 v2 = *(const float4*)&kv[k * 68 + dg * 8 + 4];
        c[0] += p * v1.x; c[1] += p * v1.y; c[2] += p * v1.z; c[3] += p * v1.w;
        c[4] += p * v2.x; c[5] += p * v2.y; c[6] += p * v2.z; c[7] += p * v2.w;
    }
    #pragma unroll
    for (int i = 0; i < 8; ++i) qs[q * 68 + dg * 8 + i] = c[i];   // ctx into qs (Q dead)
    __syncthreads();                                               // V reads + ctx writes done
    for (int idx = t; idx < 4096; idx += 128) kv[idx] = wvo[idx];  // wvo into kv
    __syncthreads();

    // proj: out[q][j] = bvo[j] + sum_d ctx[q][d]*wvo[d][j] ; thread: j = jg*8..+7
    const int jg = t & 7;
    float o[8];
    #pragma unroll
    for (int i = 0; i < 8; ++i) o[i] = bvo[jg * 8 + i];
    #pragma unroll 8
    for (int d = 0; d < 64; ++d) {
        float cv = qs[q * 68 + d];
        float4 w1 = *(const float4*)&kv[d * 64 + jg * 8];
        float4 w2 = *(const float4*)&kv[d * 64 + jg * 8 + 4];
        o[0] += cv * w1.x; o[1] += cv * w1.y; o[2] += cv * w1.z; o[3] += cv * w1.w;
        o[4] += cv * w2.x; o[5] += cv * w2.y; o[6] += cv * w2.z; o[7] += cv * w2.w;
    }
    const size_t ooff = (size_t)b * 8192 + (size_t)(q0 + q) * 64 + jg * 8;
    *(float4*)&val_out[ooff]     = make_float4(o[0], o[1], o[2], o[3]);
    *(float4*)&val_out[ooff + 4] = make_float4(o[4], o[5], o[6], o[7]);
    if (val_out2) {
        *(float4*)&val_out2[ooff]     = make_float4(o[0], o[1], o[2], o[3]);
        *(float4*)&val_out2[ooff + 4] = make_float4(o[4], o[5], o[6], o[7]);
    }
}

extern "C" void kernel_launch(void* const* d_in, const int* in_sizes, int n_in,
                              void* d_out, int out_size) {
    const float* x      = (const float*)d_in[0];
    const float* W_vote = (const float*)d_in[1];
    const float* ln_g   = (const float*)d_in[2];
    const float* ln_b   = (const float*)d_in[3];
    const float* wq1 = (const float*)d_in[4];  const float* bq1 = (const float*)d_in[5];
    const float* wk1 = (const float*)d_in[6];  const float* bk1 = (const float*)d_in[7];
    const float* wv1 = (const float*)d_in[8];  const float* bv1 = (const float*)d_in[9];
    const float* wo1 = (const float*)d_in[10]; const float* bo1 = (const float*)d_in[11];
    const float* wq2 = (const float*)d_in[12]; const float* bq2 = (const float*)d_in[13];
    const float* wk2 = (const float*)d_in[14]; const float* bk2 = (const float*)d_in[15];
    const float* wv2 = (const float*)d_in[16]; const float* bv2 = (const float*)d_in[17];
    const float* wo2 = (const float*)d_in[18]; const float* bo2 = (const float*)d_in[19];
    float* out = (float*)d_out;

    // output layout: diffused (262144) | aggregated (262144) | fwd_attn (524288) | bwd_attn (524288)
    float* out_diff = out;
    float* out_agg  = (out_size >= 524288)  ? out + 262144  : nullptr;
    float* out_fat  = (out_size >= 1048576) ? out + 524288  : nullptr;
    float* out_bat  = (out_size >= 1572864) ? out + 1048576 : nullptr;

    static int smem_set = 0;
    if (!smem_set) {
        cudaFuncSetAttribute(votes_gemm_kernel,
                             cudaFuncAttributeMaxDynamicSharedMemorySize, GEMM_SMEM);
        smem_set = 1;
    }

    // device scratch symbol addresses
    float *p_nv, *p_q, *p_k, *p_k2, *p_agg, *p_wvo, *p_bvo;
    cudaGetSymbolAddress((void**)&p_nv,  g_nv);
    cudaGetSymbolAddress((void**)&p_q,   g_q);
    cudaGetSymbolAddress((void**)&p_k,   g_k);
    cudaGetSymbolAddress((void**)&p_k2,  g_k2);
    cudaGetSymbolAddress((void**)&p_agg, g_agg);
    cudaGetSymbolAddress((void**)&p_wvo, g_wvo);
    cudaGetSymbolAddress((void**)&p_bvo, g_bvo);

    // 1) heavy GEMM: mean votes (K-split partials)
    votes_gemm_kernel<<<dim3(64, 2), 128, GEMM_SMEM>>>(x, W_vote);
    // 2) reduce + layernorm -> g_nv
    ln_kernel<<<4096, 32>>>(ln_g, ln_b);
    // 3) fused value-output weights
    wvo_kernel<<<2, dim3(64, 4)>>>(wv1, wo1, bv1, bo1, wv2, wo2, bv2, bo2);
    // 4) projections for attention 1 (+ K of attention 2)
    proj_kernel<<<512, dim3(64, 8)>>>(x,    wq1, bq1, p_q);    // Q1
    proj_kernel<<<512, dim3(64, 8)>>>(p_nv, wk1, bk1, p_k);    // K1
    proj_kernel<<<512, dim3(64, 8)>>>(x,    wk2, bk2, p_k2);   // K2
    // 5) forward attention: agg = (S1 @ x) @ wvo1 + bvo1
    attn_kernel<<<dim3(8, 32), 128>>>(p_q, p_k, x, p_wvo, p_bvo,
                                      out_fat, p_agg, out_agg);
    // 6) Q2 projection
    proj_kernel<<<512, dim3(64, 8)>>>(p_agg, wq2, bq2, p_q);
    // 7) feedback attention: diffused = (S2 @ agg) @ wvo2 + bvo2
    attn_kernel<<<dim3(8, 32), 128>>>(p_q, p_k2, p_agg, p_wvo + 4096, p_bvo + 64,
                                      out_bat, out_diff, nullptr);
}

// round 3
// speedup vs baseline: 1.6307x; 1.6307x over previous
#include <cuda_runtime.h>
#include <cuda_bf16.h>
#include <cuda_pipeline.h>
#include <math.h>

// B=32, IU=128, OU=128, ID=64, VD=64
// mean-votes GEMM: mv[b][n] = (1/128) * sum_{i,e} x[b,i,e] * W[i*524288 + n*64 + e]
// done as tf32 mma.sync: M=32 (b), N=8192 (n), K=8192 (i,e)

// ---------------- scratch ----------------
__device__ float g_part[4][32 * 8192];   // K-split partials
__device__ float g_nv[32 * 8192];        // layernormed norm_value (b, o*64+d)
__device__ float g_q[32 * 128 * 64];
__device__ float g_k[32 * 128 * 64];
__device__ float g_k2[32 * 128 * 64];
__device__ float g_agg[32 * 128 * 64];
__device__ float g_wvo[2][64 * 64];
__device__ float g_bvo[2][64];

// ---------------- tf32 helpers ----------------
__device__ __forceinline__ unsigned cvt_tf32(float f) {
    unsigned u; asm("cvt.rna.tf32.f32 %0, %1;" : "=r"(u) : "f"(f)); return u;
}
#define MMA_TF32(d, a, b)                                              \
    asm("mma.sync.aligned.m16n8k8.row.col.f32.tf32.tf32.f32 "          \
        "{%0,%1,%2,%3}, {%4,%5,%6,%7}, {%8,%9}, {%0,%1,%2,%3};"        \
        : "+f"((d)[0]), "+f"((d)[1]), "+f"((d)[2]), "+f"((d)[3])       \
        : "r"((a)[0]), "r"((a)[1]), "r"((a)[2]), "r"((a)[3]),          \
          "r"((b)[0]), "r"((b)[1]))

// ---------------- mean-votes GEMM (tensor core) ----------------
// grid (32 n-tiles, 4 ksplit), 256 threads. Block tile: m32 x n256, K_block=2048.
// Stage = 32 k's (half an i): Ws 256x32 (stride 36), Xs 32x32 (stride 36). 4-deep cp.async.
constexpr int STG_F  = 256 * 36 + 32 * 36;         // 10368 floats per stage
constexpr int GEMM_SMEM = 4 * STG_F * 4;           // 165888 B

__global__ __launch_bounds__(256, 1)
void votes_gemm_tc(const float* __restrict__ X, const float* __restrict__ W) {
    extern __shared__ float sm[];
    const int tid  = threadIdx.x;
    const int lane = tid & 31, wid = tid >> 5;
    const int n0 = blockIdx.x * 256;
    const int ks = blockIdx.y;
    const int i0 = ks * 32;

    auto load_stage = [&](int st) {
        float* Ws = sm + (st & 3) * STG_F;
        float* Xs = Ws + 256 * 36;
        const int i  = i0 + (st >> 1);
        const int e0 = (st & 1) * 32;
        const float* wsrc = W + (size_t)i * 524288 + (size_t)n0 * 64 + e0;
        #pragma unroll
        for (int cch = tid; cch < 2048; cch += 256) {       // 256 rows x 8 chunks
            int n = cch >> 3, c4 = cch & 7;
            __pipeline_memcpy_async(&Ws[n * 36 + c4 * 4], wsrc + n * 64 + c4 * 4, 16);
        }
        {
            int b = tid >> 3, c4 = tid & 7;                 // 32 rows x 8 chunks = 256
            __pipeline_memcpy_async(&Xs[b * 36 + c4 * 4],
                X + (size_t)b * 8192 + (size_t)i * 64 + e0 + c4 * 4, 16);
        }
        __pipeline_commit();
    };

    load_stage(0); load_stage(1); load_stage(2);

    float acc[2][4][4];
    #pragma unroll
    for (int h = 0; h < 2; ++h)
        #pragma unroll
        for (int g = 0; g < 4; ++g)
            #pragma unroll
            for (int k = 0; k < 4; ++k) acc[h][g][k] = 0.f;

    const int r = lane >> 2, c = lane & 3;

    for (int it = 0; it < 64; ++it) {
        if (it <= 61)      __pipeline_wait_prior(2);
        else if (it == 62) __pipeline_wait_prior(1);
        else               __pipeline_wait_prior(0);
        __syncthreads();
        if (it + 3 < 64) load_stage(it + 3);

        const float* Ws = sm + (it & 3) * STG_F;
        const float* Xs = Ws + 256 * 36;
        #pragma unroll
        for (int s = 0; s < 4; ++s) {
            const int kb = s * 8 + c;
            unsigned a[2][4], b[4][2];
            #pragma unroll
            for (int h = 0; h < 2; ++h) {
                int rr = h * 16 + r;
                a[h][0] = cvt_tf32(Xs[rr * 36 + kb]);
                a[h][1] = cvt_tf32(Xs[(rr + 8) * 36 + kb]);
                a[h][2] = cvt_tf32(Xs[rr * 36 + kb + 4]);
                a[h][3] = cvt_tf32(Xs[(rr + 8) * 36 + kb + 4]);
            }
            #pragma unroll
            for (int g = 0; g < 4; ++g) {
                int nn = wid * 32 + g * 8 + r;
                b[g][0] = cvt_tf32(Ws[nn * 36 + kb]);
                b[g][1] = cvt_tf32(Ws[nn * 36 + kb + 4]);
            }
            #pragma unroll
            for (int h = 0; h < 2; ++h)
                #pragma unroll
                for (int g = 0; g < 4; ++g)
                    MMA_TF32(acc[h][g], a[h], b[g]);
        }
    }

    float* dst = g_part[ks];
    #pragma unroll
    for (int h = 0; h < 2; ++h)
        #pragma unroll
        for (int g = 0; g < 4; ++g) {
            int bb = h * 16 + r;
            int nn = n0 + wid * 32 + g * 8 + c * 2;
            *(float2*)&dst[(size_t)bb * 8192 + nn] =
                make_float2(acc[h][g][0], acc[h][g][1]);
            *(float2*)&dst[(size_t)(bb + 8) * 8192 + nn] =
                make_float2(acc[h][g][2], acc[h][g][3]);
        }
}

// ---------------- K-split reduce + 1/128 + layernorm over d=64 ----------------
__global__ __launch_bounds__(32)
void ln_kernel(const float* __restrict__ lng, const float* __restrict__ lnb) {
    const int base = blockIdx.x * 64;         // row = b*128 + o
    const int t = threadIdx.x;
    float v0 = (g_part[0][base + t] + g_part[1][base + t] +
                g_part[2][base + t] + g_part[3][base + t]) * (1.0f / 128.0f);
    float v1 = (g_part[0][base + t + 32] + g_part[1][base + t + 32] +
                g_part[2][base + t + 32] + g_part[3][base + t + 32]) * (1.0f / 128.0f);
    float s  = v0 + v1;
    float sq = v0 * v0 + v1 * v1;
    #pragma unroll
    for (int off = 16; off; off >>= 1) {
        s  += __shfl_xor_sync(0xffffffffu, s,  off);
        sq += __shfl_xor_sync(0xffffffffu, sq, off);
    }
    float mean = s * (1.0f / 64.0f);
    float var  = sq * (1.0f / 64.0f) - mean * mean;
    float rstd = rsqrtf(var + 1e-6f);
    g_nv[base + t]      = (v0 - mean) * rstd * lng[t]      + lnb[t];
    g_nv[base + t + 32] = (v1 - mean) * rstd * lng[t + 32] + lnb[t + 32];
}

// ---------------- fused value-output weights: wvo = wv@wo, bvo = bv@wo + bo ----------------
__global__ __launch_bounds__(256)
void wvo_kernel(const float* wv1, const float* wo1, const float* bv1, const float* bo1,
                const float* wv2, const float* wo2, const float* bv2, const float* bo2) {
    const int a = blockIdx.x;
    const float* wv = a ? wv2 : wv1; const float* wo = a ? wo2 : wo1;
    const float* bv = a ? bv2 : bv1; const float* bo = a ? bo2 : bo1;
    __shared__ float wos[4096];
    const int t = threadIdx.x + threadIdx.y * 64;      // blockDim (64,4)
    for (int idx = t; idx < 4096; idx += 256) wos[idx] = wo[idx];
    __syncthreads();
    const int j = threadIdx.x;
    #pragma unroll 4
    for (int dd = 0; dd < 16; ++dd) {
        int d = threadIdx.y * 16 + dd;
        float s = 0.f;
        #pragma unroll
        for (int e = 0; e < 64; ++e) s += wv[d * 64 + e] * wos[e * 64 + j];
        g_wvo[a][d * 64 + j] = s;
    }
    if (threadIdx.y == 0) {
        float s = 0.f;
        #pragma unroll
        for (int e = 0; e < 64; ++e) s += bv[e] * wos[e * 64 + j];
        g_bvo[a][j] = s + bo[j];
    }
}

// ---------------- row projection (ILP-8): out[r,:] = in[r,:]@w + bias ----------------
// grid 128 x 32 rows, 256 thr: warp = 8 j's (broadcast w), lane = row.
__global__ __launch_bounds__(256)
void proj1_kernel(const float* __restrict__ in, const float* __restrict__ w,
                  const float* __restrict__ bias, float* __restrict__ out) {
    __shared__ float ws[4096];
    __shared__ float ins[32 * 65];
    const int tid = threadIdx.x;
    const int row0 = blockIdx.x * 32;
    for (int idx = tid; idx < 4096; idx += 256) ws[idx] = w[idx];
    for (int idx = tid; idx < 2048; idx += 256)
        ins[(idx >> 6) * 65 + (idx & 63)] = in[(size_t)row0 * 64 + idx];
    __syncthreads();
    const int lane = tid & 31, j0 = (tid >> 5) * 8;
    float acc[8];
    #pragma unroll
    for (int k = 0; k < 8; ++k) acc[k] = bias[j0 + k];
    #pragma unroll 8
    for (int e = 0; e < 64; ++e) {
        float xv = ins[lane * 65 + e];
        float4 w1 = *(const float4*)&ws[e * 64 + j0];
        float4 w2 = *(const float4*)&ws[e * 64 + j0 + 4];
        acc[0] += xv * w1.x; acc[1] += xv * w1.y; acc[2] += xv * w1.z; acc[3] += xv * w1.w;
        acc[4] += xv * w2.x; acc[5] += xv * w2.y; acc[6] += xv * w2.z; acc[7] += xv * w2.w;
    }
    float* o = out + (size_t)(row0 + lane) * 64 + j0;
    *(float4*)o       = make_float4(acc[0], acc[1], acc[2], acc[3]);
    *(float4*)(o + 4) = make_float4(acc[4], acc[5], acc[6], acc[7]);
}

// dual projection: two outputs from the same input (x -> Q1, K2)
__global__ __launch_bounds__(256)
void proj2_kernel(const float* __restrict__ in,
                  const float* __restrict__ wA, const float* __restrict__ biasA,
                  float* __restrict__ outA,
                  const float* __restrict__ wB, const float* __restrict__ biasB,
                  float* __restrict__ outB) {
    __shared__ float wsA[4096], wsB[4096];
    __shared__ float ins[32 * 65];
    const int tid = threadIdx.x;
    const int row0 = blockIdx.x * 32;
    for (int idx = tid; idx < 4096; idx += 256) { wsA[idx] = wA[idx]; wsB[idx] = wB[idx]; }
    for (int idx = tid; idx < 2048; idx += 256)
        ins[(idx >> 6) * 65 + (idx & 63)] = in[(size_t)row0 * 64 + idx];
    __syncthreads();
    const int lane = tid & 31, j0 = (tid >> 5) * 8;
    float aA[8], aB[8];
    #pragma unroll
    for (int k = 0; k < 8; ++k) { aA[k] = biasA[j0 + k]; aB[k] = biasB[j0 + k]; }
    #pragma unroll 4
    for (int e = 0; e < 64; ++e) {
        float xv = ins[lane * 65 + e];
        float4 a1 = *(const float4*)&wsA[e * 64 + j0];
        float4 a2 = *(const float4*)&wsA[e * 64 + j0 + 4];
        float4 b1 = *(const float4*)&wsB[e * 64 + j0];
        float4 b2 = *(const float4*)&wsB[e * 64 + j0 + 4];
        aA[0] += xv * a1.x; aA[1] += xv * a1.y; aA[2] += xv * a1.z; aA[3] += xv * a1.w;
        aA[4] += xv * a2.x; aA[5] += xv * a2.y; aA[6] += xv * a2.z; aA[7] += xv * a2.w;
        aB[0] += xv * b1.x; aB[1] += xv * b1.y; aB[2] += xv * b1.z; aB[3] += xv * b1.w;
        aB[4] += xv * b2.x; aB[5] += xv * b2.y; aB[6] += xv * b2.z; aB[7] += xv * b2.w;
    }
    float* oA = outA + (size_t)(row0 + lane) * 64 + j0;
    float* oB = outB + (size_t)(row0 + lane) * 64 + j0;
    *(float4*)oA       = make_float4(aA[0], aA[1], aA[2], aA[3]);
    *(float4*)(oA + 4) = make_float4(aA[4], aA[5], aA[6], aA[7]);
    *(float4*)oB       = make_float4(aB[0], aB[1], aB[2], aB[3]);
    *(float4*)(oB + 4) = make_float4(aB[4], aB[5], aB[6], aB[7]);
}

// ---------------- attention: scores=softmax(Q K^T/8); out=(S@Vsrc)@wvo + bvo ----------------
__global__ __launch_bounds__(128)
void attn_kernel(const float* __restrict__ Q, const float* __restrict__ K,
                 const float* __restrict__ Vsrc,
                 const float* __restrict__ wvo, const float* __restrict__ bvo,
                 float* scores_out, float* val_out, float* val_out2) {
    __shared__ float kv[128 * 68];
    __shared__ float sc[16 * 132];
    __shared__ float qs[16 * 68];
    const int t = threadIdx.x;
    const int b = blockIdx.y, qt = blockIdx.x;
    const int q0 = qt * 16;

    const float* Qb = Q + b * 8192 + q0 * 64;
    for (int idx = t; idx < 1024; idx += 128) qs[(idx >> 6) * 68 + (idx & 63)] = Qb[idx];
    const float* Kb = K + b * 8192;
    for (int idx = t; idx < 8192; idx += 128) kv[(idx >> 6) * 68 + (idx & 63)] = Kb[idx];
    __syncthreads();

    const int q = t >> 3, kg = t & 7;
    float acc[16];
    #pragma unroll
    for (int rep = 0; rep < 16; ++rep) acc[rep] = 0.f;
    #pragma unroll
    for (int e4 = 0; e4 < 16; ++e4) {
        float4 qv = *(const float4*)&qs[q * 68 + e4 * 4];
        #pragma unroll
        for (int rep = 0; rep < 16; ++rep) {
            float4 kvv = *(const float4*)&kv[(kg + 8 * rep) * 68 + e4 * 4];
            acc[rep] += qv.x * kvv.x + qv.y * kvv.y + qv.z * kvv.z + qv.w * kvv.w;
        }
    }
    float m = -1e30f;
    #pragma unroll
    for (int rep = 0; rep < 16; ++rep) { acc[rep] *= 0.125f; m = fmaxf(m, acc[rep]); }
    #pragma unroll
    for (int off = 1; off < 8; off <<= 1) m = fmaxf(m, __shfl_xor_sync(0xffffffffu, m, off));
    float ssum = 0.f;
    #pragma unroll
    for (int rep = 0; rep < 16; ++rep) { acc[rep] = __expf(acc[rep] - m); ssum += acc[rep]; }
    #pragma unroll
    for (int off = 1; off < 8; off <<= 1) ssum += __shfl_xor_sync(0xffffffffu, ssum, off);
    const float inv = 1.0f / ssum;
    float* so = scores_out ? scores_out + b * 16384 + (q0 + q) * 128 : nullptr;
    #pragma unroll
    for (int rep = 0; rep < 16; ++rep) {
        float p = acc[rep] * inv;
        sc[q * 132 + kg + 8 * rep] = p;
        if (so) so[kg + 8 * rep] = p;
    }
    __syncthreads();

    const float* Vb = Vsrc + b * 8192;
    for (int idx = t; idx < 8192; idx += 128) kv[(idx >> 6) * 68 + (idx & 63)] = Vb[idx];
    __syncthreads();

    const int dg = t & 7;
    float cx[8];
    #pragma unroll
    for (int i = 0; i < 8; ++i) cx[i] = 0.f;
    for (int k = 0; k < 128; ++k) {
        float p = sc[q * 132 + k];
        float4 v1 = *(const float4*)&kv[k * 68 + dg * 8];
        float4 v2 = *(const float4*)&kv[k * 68 + dg * 8 + 4];
        cx[0] += p * v1.x; cx[1] += p * v1.y; cx[2] += p * v1.z; cx[3] += p * v1.w;
        cx[4] += p * v2.x; cx[5] += p * v2.y; cx[6] += p * v2.z; cx[7] += p * v2.w;
    }
    #pragma unroll
    for (int i = 0; i < 8; ++i) qs[q * 68 + dg * 8 + i] = cx[i];
    __syncthreads();
    for (int idx = t; idx < 4096; idx += 128) kv[idx] = wvo[idx];
    __syncthreads();

    const int jg = t & 7;
    float o[8];
    #pragma unroll
    for (int i = 0; i < 8; ++i) o[i] = bvo[jg * 8 + i];
    #pragma unroll 8
    for (int d = 0; d < 64; ++d) {
        float cv = qs[q * 68 + d];
        float4 w1 = *(const float4*)&kv[d * 64 + jg * 8];
        float4 w2 = *(const float4*)&kv[d * 64 + jg * 8 + 4];
        o[0] += cv * w1.x; o[1] += cv * w1.y; o[2] += cv * w1.z; o[3] += cv * w1.w;
        o[4] += cv * w2.x; o[5] += cv * w2.y; o[6] += cv * w2.z; o[7] += cv * w2.w;
    }
    const size_t ooff = (size_t)b * 8192 + (size_t)(q0 + q) * 64 + jg * 8;
    *(float4*)&val_out[ooff]     = make_float4(o[0], o[1], o[2], o[3]);
    *(float4*)&val_out[ooff + 4] = make_float4(o[4], o[5], o[6], o[7]);
    if (val_out2) {
        *(float4*)&val_out2[ooff]     = make_float4(o[0], o[1], o[2], o[3]);
        *(float4*)&val_out2[ooff + 4] = make_float4(o[4], o[5], o[6], o[7]);
    }
}

extern "C" void kernel_launch(void* const* d_in, const int* in_sizes, int n_in,
                              void* d_out, int out_size) {
    const float* x      = (const float*)d_in[0];
    const float* W_vote = (const float*)d_in[1];
    const float* ln_g   = (const float*)d_in[2];
    const float* ln_b   = (const float*)d_in[3];
    const float* wq1 = (const float*)d_in[4];  const float* bq1 = (const float*)d_in[5];
    const float* wk1 = (const float*)d_in[6];  const float* bk1 = (const float*)d_in[7];
    const float* wv1 = (const float*)d_in[8];  const float* bv1 = (const float*)d_in[9];
    const float* wo1 = (const float*)d_in[10]; const float* bo1 = (const float*)d_in[11];
    const float* wq2 = (const float*)d_in[12]; const float* bq2 = (const float*)d_in[13];
    const float* wk2 = (const float*)d_in[14]; const float* bk2 = (const float*)d_in[15];
    const float* wv2 = (const float*)d_in[16]; const float* bv2 = (const float*)d_in[17];
    const float* wo2 = (const float*)d_in[18]; const float* bo2 = (const float*)d_in[19];
    float* out = (float*)d_out;

    float* out_diff = out;
    float* out_agg  = (out_size >= 524288)  ? out + 262144  : nullptr;
    float* out_fat  = (out_size >= 1048576) ? out + 524288  : nullptr;
    float* out_bat  = (out_size >= 1572864) ? out + 1048576 : nullptr;

    static int smem_set = 0;
    if (!smem_set) {
        cudaFuncSetAttribute(votes_gemm_tc,
                             cudaFuncAttributeMaxDynamicSharedMemorySize, GEMM_SMEM);
        smem_set = 1;
    }

    float *p_nv, *p_q, *p_k, *p_k2, *p_agg, *p_wvo, *p_bvo;
    cudaGetSymbolAddress((void**)&p_nv,  g_nv);
    cudaGetSymbolAddress((void**)&p_q,   g_q);
    cudaGetSymbolAddress((void**)&p_k,   g_k);
    cudaGetSymbolAddress((void**)&p_k2,  g_k2);
    cudaGetSymbolAddress((void**)&p_agg, g_agg);
    cudaGetSymbolAddress((void**)&p_wvo, g_wvo);
    cudaGetSymbolAddress((void**)&p_bvo, g_bvo);

    // 1) heavy GEMM (tf32 tensor cores, 4-way K-split)
    votes_gemm_tc<<<dim3(32, 4), 256, GEMM_SMEM>>>(x, W_vote);
    // 2) reduce + layernorm -> g_nv
    ln_kernel<<<4096, 32>>>(ln_g, ln_b);
    // 3) fused value-output weights
    wvo_kernel<<<2, dim3(64, 4)>>>(wv1, wo1, bv1, bo1, wv2, wo2, bv2, bo2);
    // 4) projections
    proj2_kernel<<<128, 256>>>(x, wq1, bq1, p_q, wk2, bk2, p_k2);   // Q1, K2
    proj1_kernel<<<128, 256>>>(p_nv, wk1, bk1, p_k);                // K1
    // 5) forward attention: agg = (S1 @ x) @ wvo1 + bvo1
    attn_kernel<<<dim3(8, 32), 128>>>(p_q, p_k, x, p_wvo, p_bvo,
                                      out_fat, p_agg, out_agg);
    // 6) Q2 projection
    proj1_kernel<<<128, 256>>>(p_agg, wq2, bq2, p_q);
    // 7) feedback attention: diffused = (S2 @ agg) @ wvo2 + bvo2
    attn_kernel<<<dim3(8, 32), 128>>>(p_q, p_k2, p_agg, p_wvo + 4096, p_bvo + 64,
                                      out_bat, out_diff, nullptr);
}

// round 5
// speedup vs baseline: 1.7734x; 1.0875x over previous
#include <cuda_runtime.h>
#include <cuda_bf16.h>
#include <cuda_pipeline.h>
#include <math.h>
#include <cstdint>

// B=32, IU=128, OU=128, ID=64, VD=64
// mean-votes GEMM: mv[b][n] = (1/128) sum_{i,e} x[b,i,e] * W[i*524288 + n*64 + e]
// M=32, N=8192, K=8192 via mma.sync m16n8k16 bf16 (fp32 accum).

// ---------------- scratch ----------------
__device__ float g_part[4][32 * 8192];   // K-split partials
__device__ float g_q[32 * 128 * 64];
__device__ float g_k[32 * 128 * 64];
__device__ float g_k2[32 * 128 * 64];
__device__ float g_agg[32 * 128 * 64];
__device__ float g_wvo[2][64 * 64];
__device__ float g_bvo[2][64];

// ---------------- bf16 helpers ----------------
__device__ __forceinline__ unsigned pack_bf16(float lo, float hi) {
    unsigned r;
    asm("cvt.rn.bf16x2.f32 %0, %1, %2;" : "=r"(r) : "f"(hi), "f"(lo));  // first src -> high half
    return r;
}
#define MMA_BF16(d, a, b)                                                  \
    asm("mma.sync.aligned.m16n8k16.row.col.f32.bf16.bf16.f32 "             \
        "{%0,%1,%2,%3}, {%4,%5,%6,%7}, {%8,%9}, {%0,%1,%2,%3};"            \
        : "+f"((d)[0]), "+f"((d)[1]), "+f"((d)[2]), "+f"((d)[3])           \
        : "r"((a)[0]), "r"((a)[1]), "r"((a)[2]), "r"((a)[3]),              \
          "r"((b)[0]), "r"((b)[1]))

// ---------------- mean-votes GEMM ----------------
// grid (32 n-tiles, 4 ksplit), 256 threads. CTA tile m32 x n256, K_block=2048.
// Stage = 32 k's (half an i). 4-deep cp.async pipeline. smem row stride 40.
constexpr int RSTR = 40;
constexpr int STG_F = 256 * RSTR + 32 * RSTR;        // 11520 floats / stage
constexpr int GEMM_SMEM = 4 * STG_F * 4;             // 184320 B

__global__ __launch_bounds__(256, 1)
void votes_gemm_bf16(const float* __restrict__ X, const float* __restrict__ W) {
    extern __shared__ float sm[];
    const int tid  = threadIdx.x;
    const int lane = tid & 31, wid = tid >> 5;
    const int n0 = blockIdx.x * 256;
    const int ks = blockIdx.y;
    const int i0 = ks * 32;

    auto load_stage = [&](int st) {
        float* Ws = sm + (st & 3) * STG_F;
        float* Xs = Ws + 256 * RSTR;
        const int i  = i0 + (st >> 1);
        const int e0 = (st & 1) * 32;
        const float* wb = W + (size_t)i * 524288 + (size_t)n0 * 64 + e0;
        #pragma unroll
        for (int c = tid; c < 2048; c += 256) {          // 256 rows x 8 x 16B
            int n = c >> 3, g = c & 7;
            __pipeline_memcpy_async(&Ws[n * RSTR + g * 4], wb + n * 64 + g * 4, 16);
        }
        {
            int b = tid >> 3, g = tid & 7;               // 32 rows x 8 x 16B
            __pipeline_memcpy_async(&Xs[b * RSTR + g * 4],
                X + (size_t)b * 8192 + (size_t)i * 64 + e0 + g * 4, 16);
        }
        __pipeline_commit();
    };

    load_stage(0); load_stage(1); load_stage(2);

    float acc[2][4][4];
    #pragma unroll
    for (int h = 0; h < 2; ++h)
        #pragma unroll
        for (int g = 0; g < 4; ++g)
            #pragma unroll
            for (int k = 0; k < 4; ++k) acc[h][g][k] = 0.f;

    const int r = lane >> 2, c = lane & 3;

    for (int it = 0; it < 64; ++it) {
        if (it <= 61)      __pipeline_wait_prior(2);
        else if (it == 62) __pipeline_wait_prior(1);
        else               __pipeline_wait_prior(0);
        __syncthreads();
        if (it + 3 < 64) load_stage(it + 3);

        const float* Ws = sm + (it & 3) * STG_F;
        const float* Xs = Ws + 256 * RSTR;
        #pragma unroll
        for (int s = 0; s < 2; ++s) {                    // 2 x k16 per stage
            const int k0 = s * 16 + 2 * c;
            unsigned a[2][4], bf[4][2];
            #pragma unroll
            for (int h = 0; h < 2; ++h) {
                const int m0 = h * 16 + r;
                float2 p0 = *(const float2*)&Xs[m0 * RSTR + k0];
                float2 p1 = *(const float2*)&Xs[(m0 + 8) * RSTR + k0];
                float2 p2 = *(const float2*)&Xs[m0 * RSTR + k0 + 8];
                float2 p3 = *(const float2*)&Xs[(m0 + 8) * RSTR + k0 + 8];
                a[h][0] = pack_bf16(p0.x, p0.y);
                a[h][1] = pack_bf16(p1.x, p1.y);
                a[h][2] = pack_bf16(p2.x, p2.y);
                a[h][3] = pack_bf16(p3.x, p3.y);
            }
            #pragma unroll
            for (int g = 0; g < 4; ++g) {
                const int nrow = wid * 32 + g * 8 + r;
                float2 q0 = *(const float2*)&Ws[nrow * RSTR + k0];
                float2 q1 = *(const float2*)&Ws[nrow * RSTR + k0 + 8];
                bf[g][0] = pack_bf16(q0.x, q0.y);
                bf[g][1] = pack_bf16(q1.x, q1.y);
            }
            #pragma unroll
            for (int h = 0; h < 2; ++h)
                #pragma unroll
                for (int g = 0; g < 4; ++g)
                    MMA_BF16(acc[h][g], a[h], bf[g]);
        }
    }

    float* dst = g_part[ks];
    #pragma unroll
    for (int h = 0; h < 2; ++h)
        #pragma unroll
        for (int g = 0; g < 4; ++g) {
            const int m0 = h * 16 + r;
            const int nn = n0 + wid * 32 + g * 8 + 2 * c;
            *(float2*)&dst[(size_t)m0 * 8192 + nn] =
                make_float2(acc[h][g][0], acc[h][g][1]);
            *(float2*)&dst[(size_t)(m0 + 8) * 8192 + nn] =
                make_float2(acc[h][g][2], acc[h][g][3]);
        }
}

// ---------------- fused: K-split reduce + 1/128 + layernorm + K1 projection ----------------
// block 256 (8 warps = 8 rows), grid 512. Writes g_k = layernorm(mv) @ wk1 + bk1.
__global__ __launch_bounds__(256)
void ln_k1_kernel(const float* __restrict__ lng, const float* __restrict__ lnb,
                  const float* __restrict__ wk1, const float* __restrict__ bk1) {
    __shared__ float ws[4096];
    __shared__ float rows[8][68];
    const int tid = threadIdx.x;
    const int w = tid >> 5, t = tid & 31;
    const int row = blockIdx.x * 8 + w;
    const int base = row * 64;

    for (int idx = tid; idx < 4096; idx += 256) ws[idx] = wk1[idx];

    float v0 = (g_part[0][base + t] + g_part[1][base + t] +
                g_part[2][base + t] + g_part[3][base + t]) * (1.0f / 128.0f);
    float v1 = (g_part[0][base + t + 32] + g_part[1][base + t + 32] +
                g_part[2][base + t + 32] + g_part[3][base + t + 32]) * (1.0f / 128.0f);
    float s  = v0 + v1;
    float sq = v0 * v0 + v1 * v1;
    #pragma unroll
    for (int off = 16; off; off >>= 1) {
        s  += __shfl_xor_sync(0xffffffffu, s,  off);
        sq += __shfl_xor_sync(0xffffffffu, sq, off);
    }
    float mean = s * (1.0f / 64.0f);
    float var  = sq * (1.0f / 64.0f) - mean * mean;
    float rstd = rsqrtf(var + 1e-6f);
    rows[w][t]      = (v0 - mean) * rstd * lng[t]      + lnb[t];
    rows[w][t + 32] = (v1 - mean) * rstd * lng[t + 32] + lnb[t + 32];
    __syncthreads();

    float a0 = bk1[t], a1 = bk1[t + 32];
    #pragma unroll 8
    for (int e = 0; e < 64; ++e) {
        float rv = rows[w][e];
        a0 += rv * ws[e * 64 + t];
        a1 += rv * ws[e * 64 + t + 32];
    }
    g_k[base + t]      = a0;
    g_k[base + t + 32] = a1;
}

// ---------------- fused value-output weights: wvo = wv@wo, bvo = bv@wo + bo ----------------
__global__ __launch_bounds__(256)
void wvo_kernel(const float* wv1, const float* wo1, const float* bv1, const float* bo1,
                const float* wv2, const float* wo2, const float* bv2, const float* bo2) {
    const int a = blockIdx.x;
    const float* wv = a ? wv2 : wv1; const float* wo = a ? wo2 : wo1;
    const float* bv = a ? bv2 : bv1; const float* bo = a ? bo2 : bo1;
    __shared__ float wos[4096];
    const int t = threadIdx.x + threadIdx.y * 64;      // blockDim (64,4)
    for (int idx = t; idx < 4096; idx += 256) wos[idx] = wo[idx];
    __syncthreads();
    const int j = threadIdx.x;
    #pragma unroll 4
    for (int dd = 0; dd < 16; ++dd) {
        int d = threadIdx.y * 16 + dd;
        float s = 0.f;
        #pragma unroll
        for (int e = 0; e < 64; ++e) s += wv[d * 64 + e] * wos[e * 64 + j];
        g_wvo[a][d * 64 + j] = s;
    }
    if (threadIdx.y == 0) {
        float s = 0.f;
        #pragma unroll
        for (int e = 0; e < 64; ++e) s += bv[e] * wos[e * 64 + j];
        g_bvo[a][j] = s + bo[j];
    }
}

// ---------------- dual projection: x -> Q1, K2 ----------------
__global__ __launch_bounds__(256)
void proj2_kernel(const float* __restrict__ in,
                  const float* __restrict__ wA, const float* __restrict__ biasA,
                  float* __restrict__ outA,
                  const float* __restrict__ wB, const float* __restrict__ biasB,
                  float* __restrict__ outB) {
    __shared__ float wsA[4096], wsB[4096];
    __shared__ float ins[32 * 65];
    const int tid = threadIdx.x;
    const int row0 = blockIdx.x * 32;
    for (int idx = tid; idx < 4096; idx += 256) { wsA[idx] = wA[idx]; wsB[idx] = wB[idx]; }
    for (int idx = tid; idx < 2048; idx += 256)
        ins[(idx >> 6) * 65 + (idx & 63)] = in[(size_t)row0 * 64 + idx];
    __syncthreads();
    const int lane = tid & 31, j0 = (tid >> 5) * 8;
    float aA[8], aB[8];
    #pragma unroll
    for (int k = 0; k < 8; ++k) { aA[k] = biasA[j0 + k]; aB[k] = biasB[j0 + k]; }
    #pragma unroll 4
    for (int e = 0; e < 64; ++e) {
        float xv = ins[lane * 65 + e];
        float4 a1 = *(const float4*)&wsA[e * 64 + j0];
        float4 a2 = *(const float4*)&wsA[e * 64 + j0 + 4];
        float4 b1 = *(const float4*)&wsB[e * 64 + j0];
        float4 b2 = *(const float4*)&wsB[e * 64 + j0 + 4];
        aA[0] += xv * a1.x; aA[1] += xv * a1.y; aA[2] += xv * a1.z; aA[3] += xv * a1.w;
        aA[4] += xv * a2.x; aA[5] += xv * a2.y; aA[6] += xv * a2.z; aA[7] += xv * a2.w;
        aB[0] += xv * b1.x; aB[1] += xv * b1.y; aB[2] += xv * b1.z; aB[3] += xv * b1.w;
        aB[4] += xv * b2.x; aB[5] += xv * b2.y; aB[6] += xv * b2.z; aB[7] += xv * b2.w;
    }
    float* oA = outA + (size_t)(row0 + lane) * 64 + j0;
    float* oB = outB + (size_t)(row0 + lane) * 64 + j0;
    *(float4*)oA       = make_float4(aA[0], aA[1], aA[2], aA[3]);
    *(float4*)(oA + 4) = make_float4(aA[4], aA[5], aA[6], aA[7]);
    *(float4*)oB       = make_float4(aB[0], aB[1], aB[2], aB[3]);
    *(float4*)(oB + 4) = make_float4(aB[4], aB[5], aB[6], aB[7]);
}

// ---------------- attention (+ optional fused Q2 projection) ----------------
// scores = softmax(Q K^T / 8); out = (S @ Vsrc) @ wvo + bvo; q2 = out @ wq2 + bq2
__global__ __launch_bounds__(128)
void attn_kernel(const float* __restrict__ Q, const float* __restrict__ K,
                 const float* __restrict__ Vsrc,
                 const float* __restrict__ wvo, const float* __restrict__ bvo,
                 float* scores_out, float* val_out, float* val_out2,
                 const float* __restrict__ wq2, const float* __restrict__ bq2,
                 float* __restrict__ q2_out) {
    __shared__ float kv[128 * 68];
    __shared__ float sc[16 * 132];
    __shared__ float qs[16 * 68];
    const int t = threadIdx.x;
    const int b = blockIdx.y, qt = blockIdx.x;
    const int q0 = qt * 16;

    const float* Qb = Q + b * 8192 + q0 * 64;
    for (int idx = t; idx < 1024; idx += 128) qs[(idx >> 6) * 68 + (idx & 63)] = Qb[idx];
    const float* Kb = K + b * 8192;
    for (int idx = t; idx < 8192; idx += 128) kv[(idx >> 6) * 68 + (idx & 63)] = Kb[idx];
    __syncthreads();

    const int q = t >> 3, kg = t & 7;
    float acc[16];
    #pragma unroll
    for (int rep = 0; rep < 16; ++rep) acc[rep] = 0.f;
    #pragma unroll
    for (int e4 = 0; e4 < 16; ++e4) {
        float4 qv = *(const float4*)&qs[q * 68 + e4 * 4];
        #pragma unroll
        for (int rep = 0; rep < 16; ++rep) {
            float4 kvv = *(const float4*)&kv[(kg + 8 * rep) * 68 + e4 * 4];
            acc[rep] += qv.x * kvv.x + qv.y * kvv.y + qv.z * kvv.z + qv.w * kvv.w;
        }
    }
    float m = -1e30f;
    #pragma unroll
    for (int rep = 0; rep < 16; ++rep) { acc[rep] *= 0.125f; m = fmaxf(m, acc[rep]); }
    #pragma unroll
    for (int off = 1; off < 8; off <<= 1) m = fmaxf(m, __shfl_xor_sync(0xffffffffu, m, off));
    float ssum = 0.f;
    #pragma unroll
    for (int rep = 0; rep < 16; ++rep) { acc[rep] = __expf(acc[rep] - m); ssum += acc[rep]; }
    #pragma unroll
    for (int off = 1; off < 8; off <<= 1) ssum += __shfl_xor_sync(0xffffffffu, ssum, off);
    const float inv = 1.0f / ssum;
    float* so = scores_out ? scores_out + b * 16384 + (q0 + q) * 128 : nullptr;
    #pragma unroll
    for (int rep = 0; rep < 16; ++rep) {
        float p = acc[rep] * inv;
        sc[q * 132 + kg + 8 * rep] = p;
        if (so) so[kg + 8 * rep] = p;
    }
    __syncthreads();

    const float* Vb = Vsrc + b * 8192;
    for (int idx = t; idx < 8192; idx += 128) kv[(idx >> 6) * 68 + (idx & 63)] = Vb[idx];
    __syncthreads();

    const int dg = t & 7;
    float cx[8];
    #pragma unroll
    for (int i = 0; i < 8; ++i) cx[i] = 0.f;
    for (int k = 0; k < 128; ++k) {
        float p = sc[q * 132 + k];
        float4 v1 = *(const float4*)&kv[k * 68 + dg * 8];
        float4 v2 = *(const float4*)&kv[k * 68 + dg * 8 + 4];
        cx[0] += p * v1.x; cx[1] += p * v1.y; cx[2] += p * v1.z; cx[3] += p * v1.w;
        cx[4] += p * v2.x; cx[5] += p * v2.y; cx[6] += p * v2.z; cx[7] += p * v2.w;
    }
    #pragma unroll
    for (int i = 0; i < 8; ++i) qs[q * 68 + dg * 8 + i] = cx[i];
    __syncthreads();
    for (int idx = t; idx < 4096; idx += 128) kv[idx] = wvo[idx];
    __syncthreads();

    const int jg = t & 7;
    float o[8];
    #pragma unroll
    for (int i = 0; i < 8; ++i) o[i] = bvo[jg * 8 + i];
    #pragma unroll 8
    for (int d = 0; d < 64; ++d) {
        float cv = qs[q * 68 + d];
        float4 w1 = *(const float4*)&kv[d * 64 + jg * 8];
        float4 w2 = *(const float4*)&kv[d * 64 + jg * 8 + 4];
        o[0] += cv * w1.x; o[1] += cv * w1.y; o[2] += cv * w1.z; o[3] += cv * w1.w;
        o[4] += cv * w2.x; o[5] += cv * w2.y; o[6] += cv * w2.z; o[7] += cv * w2.w;
    }
    const size_t ooff = (size_t)b * 8192 + (size_t)(q0 + q) * 64 + jg * 8;
    *(float4*)&val_out[ooff]     = make_float4(o[0], o[1], o[2], o[3]);
    *(float4*)&val_out[ooff + 4] = make_float4(o[4], o[5], o[6], o[7]);
    if (val_out2) {
        *(float4*)&val_out2[ooff]     = make_float4(o[0], o[1], o[2], o[3]);
        *(float4*)&val_out2[ooff + 4] = make_float4(o[4], o[5], o[6], o[7]);
    }

    // fused Q2 projection: q2 = out @ wq2 + bq2 (each block owns its 16 rows of q2_out)
    if (q2_out) {
        __syncthreads();
        #pragma unroll
        for (int i = 0; i < 8; ++i) qs[q * 68 + jg * 8 + i] = o[i];
        for (int idx = t; idx < 4096; idx += 128) kv[idx] = wq2[idx];
        __syncthreads();
        float o2[8];
        #pragma unroll
        for (int i = 0; i < 8; ++i) o2[i] = bq2[jg * 8 + i];
        #pragma unroll 8
        for (int d = 0; d < 64; ++d) {
            float cv = qs[q * 68 + d];
            float4 w1 = *(const float4*)&kv[d * 64 + jg * 8];
            float4 w2 = *(const float4*)&kv[d * 64 + jg * 8 + 4];
            o2[0] += cv * w1.x; o2[1] += cv * w1.y; o2[2] += cv * w1.z; o2[3] += cv * w1.w;
            o2[4] += cv * w2.x; o2[5] += cv * w2.y; o2[6] += cv * w2.z; o2[7] += cv * w2.w;
        }
        *(float4*)&q2_out[ooff]     = make_float4(o2[0], o2[1], o2[2], o2[3]);
        *(float4*)&q2_out[ooff + 4] = make_float4(o2[4], o2[5], o2[6], o2[7]);
    }
}

extern "C" void kernel_launch(void* const* d_in, const int* in_sizes, int n_in,
                              void* d_out, int out_size) {
    const float* x      = (const float*)d_in[0];
    const float* W_vote = (const float*)d_in[1];
    const float* ln_g   = (const float*)d_in[2];
    const float* ln_b   = (const float*)d_in[3];
    const float* wq1 = (const float*)d_in[4];  const float* bq1 = (const float*)d_in[5];
    const float* wk1 = (const float*)d_in[6];  const float* bk1 = (const float*)d_in[7];
    const float* wv1 = (const float*)d_in[8];  const float* bv1 = (const float*)d_in[9];
    const float* wo1 = (const float*)d_in[10]; const float* bo1 = (const float*)d_in[11];
    const float* wq2 = (const float*)d_in[12]; const float* bq2 = (const float*)d_in[13];
    const float* wk2 = (const float*)d_in[14]; const float* bk2 = (const float*)d_in[15];
    const float* wv2 = (const float*)d_in[16]; const float* bv2 = (const float*)d_in[17];
    const float* wo2 = (const float*)d_in[18]; const float* bo2 = (const float*)d_in[19];
    float* out = (float*)d_out;

    float* out_diff = out;
    float* out_agg  = (out_size >= 524288)  ? out + 262144  : nullptr;
    float* out_fat  = (out_size >= 1048576) ? out + 524288  : nullptr;
    float* out_bat  = (out_size >= 1572864) ? out + 1048576 : nullptr;

    static int smem_set = 0;
    if (!smem_set) {
        cudaFuncSetAttribute(votes_gemm_bf16,
                             cudaFuncAttributeMaxDynamicSharedMemorySize, GEMM_SMEM);
        smem_set = 1;
    }

    float *p_q, *p_k, *p_k2, *p_agg, *p_wvo, *p_bvo;
    cudaGetSymbolAddress((void**)&p_q,   g_q);
    cudaGetSymbolAddress((void**)&p_k,   g_k);
    cudaGetSymbolAddress((void**)&p_k2,  g_k2);
    cudaGetSymbolAddress((void**)&p_agg, g_agg);
    cudaGetSymbolAddress((void**)&p_wvo, g_wvo);
    cudaGetSymbolAddress((void**)&p_bvo, g_bvo);

    // independent prep
    wvo_kernel<<<2, dim3(64, 4)>>>(wv1, wo1, bv1, bo1, wv2, wo2, bv2, bo2);
    proj2_kernel<<<128, 256>>>(x, wq1, bq1, p_q, wk2, bk2, p_k2);   // Q1, K2
    // heavy GEMM (bf16 tensor cores, 4-way K-split)
    votes_gemm_bf16<<<dim3(32, 4), 256, GEMM_SMEM>>>(x, W_vote);
    // fused reduce + layernorm + K1 projection
    ln_k1_kernel<<<512, 256>>>(ln_g, ln_b, wk1, bk1);
    // forward attention (+ fused Q2 projection into p_q)
    attn_kernel<<<dim3(8, 32), 128>>>(p_q, p_k, x, p_wvo, p_bvo,
                                      out_fat, p_agg, out_agg, wq2, bq2, p_q);
    // feedback attention
    attn_kernel<<<dim3(8, 32), 128>>>(p_q, p_k2, p_agg, p_wvo + 4096, p_bvo + 64,
                                      out_bat, out_diff, nullptr, nullptr, nullptr, nullptr);
}